// round 9
// baseline (speedup 1.0000x reference)
#include <cuda_runtime.h>
#include <math.h>
#include <stdint.h>

// Problem constants
#define BB    2
#define TT    1024
#define DD    1024
#define HH    16
#define DHH   64
#define NLAY  4
#define NLEV  8
#define DFF   4096
#define NROWS (BB*TT)
#define FMAXV 3.402823466e38f

// Scratch (device globals — no allocation allowed)
__device__ float g_h[NROWS * DD];
__device__ float g_qkv[NROWS * 3 * DD];
__device__ float g_attn[NROWS * DD];
__device__ float g_f1[NROWS * DFF];
// tf32-pre-rounded weights (per launch)
__device__ float g_wqkv[NLAY * DD * 3 * DD];
__device__ float g_wout[NLAY * DD * DD];
__device__ float g_w1[NLAY * DD * DFF];
__device__ float g_w2[NLAY * DFF * DD];

__device__ __forceinline__ float gelu_exact(float x) {
    return 0.5f * x * (1.0f + erff(x * 0.70710678118654752f));
}

__device__ __forceinline__ float cvt_tf32(float x) {
    uint32_t u;
    asm("cvt.rna.tf32.f32 %0, %1;" : "=r"(u) : "f"(x));
    return __uint_as_float(u);
}

__device__ __forceinline__ void cp_async16(void* smem, const void* gmem) {
    uint32_t s = (uint32_t)__cvta_generic_to_shared(smem);
    asm volatile("cp.async.cg.shared.global [%0], [%1], 16;" :: "r"(s), "l"(gmem));
}

// ---------------------------------------------------------------------------
// Weight pre-round: out[i] = tf32(in[i]), vectorized
// ---------------------------------------------------------------------------
__global__ void round_weights(const float* __restrict__ in, float* __restrict__ out,
                              int n4) {
    int i = blockIdx.x * blockDim.x + threadIdx.x;
    int stride = gridDim.x * blockDim.x;
    for (; i < n4; i += stride) {
        float4 v = ((const float4*)in)[i];
        v.x = cvt_tf32(v.x); v.y = cvt_tf32(v.y);
        v.z = cvt_tf32(v.z); v.w = cvt_tf32(v.w);
        ((float4*)out)[i] = v;
    }
}

// ---------------------------------------------------------------------------
// AdaLN  (output tf32-pre-rounded: it only feeds GEMM A operands)
// ---------------------------------------------------------------------------
__global__ void adaln_kernel(const float* __restrict__ x, const float* __restrict__ m,
                             const int* __restrict__ l, const float* __restrict__ emb,
                             float* __restrict__ out) {
    int row = blockIdx.x;
    int b = row / TT;
    float mv = m[row];
    const float* xr = x + (size_t)row * DD;
    float* orow = out + (size_t)row * DD;
    int tid = threadIdx.x;

    float v[4];
    float s = 0.f, ss = 0.f;
#pragma unroll
    for (int u = 0; u < 4; u++) {
        v[u] = xr[tid + u * 256];
        s += v[u];
        ss += v[u] * v[u];
    }
    __shared__ float sh1[256];
    __shared__ float sh2[256];
    sh1[tid] = s; sh2[tid] = ss;
    __syncthreads();
    for (int stp = 128; stp > 0; stp >>= 1) {
        if (tid < stp) { sh1[tid] += sh1[tid + stp]; sh2[tid] += sh2[tid + stp]; }
        __syncthreads();
    }
    float mu  = sh1[0] * (1.0f / DD);
    float var = sh2[0] * (1.0f / DD) - mu * mu;
    float rinv = rsqrtf(var + 1e-5f);

    const float* g = emb + (size_t)l[b] * (2 * DD);
#pragma unroll
    for (int u = 0; u < 4; u++) {
        int d = tid + u * 256;
        float hn = (v[u] - mu) * rinv;
        float h = 2.0f * (1.0f - 0.1f * hn) * hn;
        orow[d] = cvt_tf32((expf(g[d]) * h + g[DD + d]) * mv);
    }
}

// ---------------------------------------------------------------------------
// tf32 tensor-core GEMM, 3-stage cp.async ring, ONE sync per k-iter.
// A and W are both pre-rounded tf32 (raw-bit fragment loads, no cvt).
// BM: 128 or 64. N-tile 128, BK=32, 256 threads.
// EPI: 0 = none (store tf32), 1 = GELU (store tf32),
//      2 = residual+mask  C = (res + gemm + bias)*m[row]  (full fp32 store)
// ---------------------------------------------------------------------------
template <int BM, int EPI>
__global__ void __launch_bounds__(256, 2)
gemm_tf32(const float* __restrict__ A, const float* __restrict__ W,
          const float* __restrict__ bias, const float* __restrict__ res,
          const float* __restrict__ m, float* __restrict__ C,
          int M, int N, int K) {
    constexpr int MI = BM / 32;
    __shared__ __align__(16) float As[3][BM][36];
    __shared__ __align__(16) float Bs[3][32][136];

    int tid  = threadIdx.x;
    int warp = tid >> 5, lane = tid & 31;
    int g = lane >> 2, t = lane & 3;
    int warpm = warp >> 2, warpn = warp & 3;
    int row0 = blockIdx.y * BM, col0 = blockIdx.x * 128;

    float acc[MI][4][4] = {};

    int ar = tid >> 3, ac4 = (tid & 7) * 4;
    int br = tid >> 5, bc4 = (tid & 31) * 4;

#define ISSUE_TILE(slot, k0)                                                    \
    {                                                                           \
        _Pragma("unroll")                                                       \
        for (int i = 0; i < BM / 32; i++)                                       \
            cp_async16(&As[slot][ar + i * 32][ac4],                             \
                       A + (size_t)(row0 + ar + i * 32) * K + (k0) + ac4);      \
        _Pragma("unroll")                                                       \
        for (int i = 0; i < 4; i++)                                             \
            cp_async16(&Bs[slot][br + i * 8][bc4],                              \
                       W + (size_t)((k0) + br + i * 8) * N + col0 + bc4);       \
        asm volatile("cp.async.commit_group;");                                 \
    }

    ISSUE_TILE(0, 0)
    ISSUE_TILE(1, 32)

    int nit = K / 32;
    for (int it = 0; it < nit; it++) {
        if (it < nit - 1) {
            asm volatile("cp.async.wait_group 1;");
        } else {
            asm volatile("cp.async.wait_group 0;");
        }
        __syncthreads();
        // prefetch tile it+2 into the slot computed at it-1 (all threads passed
        // the sync after finishing it-1, so the slot is free)
        if (it + 2 < nit) {
            int slot = (it + 2) % 3;
            int k0 = (it + 2) * 32;
            ISSUE_TILE(slot, k0)
        }
        int buf = it % 3;

#pragma unroll
        for (int kk = 0; kk < 32; kk += 8) {
            uint32_t af[MI][4], bf[4][2];
#pragma unroll
            for (int mi = 0; mi < MI; mi++) {
                int rb = warpm * (BM / 2) + mi * 16 + g;
                af[mi][0] = __float_as_uint(As[buf][rb    ][kk + t    ]);
                af[mi][1] = __float_as_uint(As[buf][rb + 8][kk + t    ]);
                af[mi][2] = __float_as_uint(As[buf][rb    ][kk + t + 4]);
                af[mi][3] = __float_as_uint(As[buf][rb + 8][kk + t + 4]);
            }
#pragma unroll
            for (int ni = 0; ni < 4; ni++) {
                int cb = warpn * 32 + ni * 8 + g;
                bf[ni][0] = __float_as_uint(Bs[buf][kk + t    ][cb]);
                bf[ni][1] = __float_as_uint(Bs[buf][kk + t + 4][cb]);
            }
#pragma unroll
            for (int mi = 0; mi < MI; mi++)
#pragma unroll
                for (int ni = 0; ni < 4; ni++) {
                    asm volatile(
                        "mma.sync.aligned.m16n8k8.row.col.f32.tf32.tf32.f32 "
                        "{%0,%1,%2,%3}, {%4,%5,%6,%7}, {%8,%9}, {%0,%1,%2,%3};"
                        : "+f"(acc[mi][ni][0]), "+f"(acc[mi][ni][1]),
                          "+f"(acc[mi][ni][2]), "+f"(acc[mi][ni][3])
                        : "r"(af[mi][0]), "r"(af[mi][1]), "r"(af[mi][2]), "r"(af[mi][3]),
                          "r"(bf[ni][0]), "r"(bf[ni][1]));
                }
        }
    }
#undef ISSUE_TILE

#pragma unroll
    for (int mi = 0; mi < MI; mi++) {
        int r0 = row0 + warpm * (BM / 2) + mi * 16 + g;
        int r1 = r0 + 8;
        float m0 = (EPI == 2) ? m[r0] : 0.f;
        float m1 = (EPI == 2) ? m[r1] : 0.f;
#pragma unroll
        for (int ni = 0; ni < 4; ni++) {
            int cb = col0 + warpn * 32 + ni * 8 + 2 * t;
            float v0 = acc[mi][ni][0], v1 = acc[mi][ni][1];
            float v2 = acc[mi][ni][2], v3 = acc[mi][ni][3];
            if (bias) {
                float b0 = bias[cb], b1 = bias[cb + 1];
                v0 += b0; v1 += b1; v2 += b0; v3 += b1;
            }
            if (EPI == 1) {
                v0 = gelu_exact(v0); v1 = gelu_exact(v1);
                v2 = gelu_exact(v2); v3 = gelu_exact(v3);
            }
            if (EPI == 2) {
                const float* rr0 = res + (size_t)r0 * N + cb;
                const float* rr1 = res + (size_t)r1 * N + cb;
                v0 = (rr0[0] + v0) * m0; v1 = (rr0[1] + v1) * m0;
                v2 = (rr1[0] + v2) * m1; v3 = (rr1[1] + v3) * m1;
            } else {
                v0 = cvt_tf32(v0); v1 = cvt_tf32(v1);
                v2 = cvt_tf32(v2); v3 = cvt_tf32(v3);
            }
            *(float2*)(C + (size_t)r0 * N + cb) = make_float2(v0, v1);
            *(float2*)(C + (size_t)r1 * N + cb) = make_float2(v2, v3);
        }
    }
}

// ---------------------------------------------------------------------------
// Flash attention (tf32 MMA): 8 warps; warp w owns rows [w*16, w*16+16)
// across all 64 j-columns. qkv is pre-rounded tf32 (raw copies).
// smem: Q[128][68] | K[64][68] | V[64][68] | P[128][68]
// ---------------------------------------------------------------------------
#define FA_SMEM ((128*68 + 64*68 + 64*68 + 128*68) * 4)

__global__ void __launch_bounds__(256)
flash_kernel(const float* __restrict__ qkv, const float* __restrict__ mk,
             float* __restrict__ O) {
    extern __shared__ float sm[];
    float (*Qs)[68] = (float(*)[68])sm;
    float (*Ks)[68] = (float(*)[68])(sm + 128 * 68);
    float (*Vs)[68] = (float(*)[68])(sm + 128 * 68 + 64 * 68);
    float (*Ps)[68] = (float(*)[68])(sm + 128 * 68 + 2 * 64 * 68);

    int z = blockIdx.y; int b = z >> 4; int h = z & 15;
    int it = gridDim.x - 1 - blockIdx.x;
    int i0 = it * 128;
    int tid = threadIdx.x;
    int warp = tid >> 5, lane = tid & 31;
    int g = lane >> 2, t = lane & 3;
    int wrow = warp * 16;

    const float* qb = qkv + (size_t)b * TT * 3 * DD + h * DHH;
    const float* kb = qb + DD;
    const float* vb = qb + 2 * DD;
    const float* mrow = mk + b * TT;

#pragma unroll
    for (int i = 0; i < 8; i++) {
        int idx = tid + i * 256;
        int r = idx >> 4, c4 = (idx & 15) * 4;
        *(float4*)&Qs[r][c4] = *(const float4*)(qb + (size_t)(i0 + r) * (3 * DD) + c4);
    }

    float oacc[8][4] = {};
    float mst0 = -FMAXV, mst1 = -FMAXV;
    float lst0 = 0.f,    lst1 = 0.f;

    int jend = i0 + 128;
    for (int j0 = 0; j0 < jend; j0 += 64) {
        __syncthreads();
#pragma unroll
        for (int i = 0; i < 4; i++) {
            int idx = tid + i * 256;
            int r = idx >> 4, c4 = (idx & 15) * 4;
            *(float4*)&Ks[r][c4] = *(const float4*)(kb + (size_t)(j0 + r) * (3 * DD) + c4);
            *(float4*)&Vs[r][c4] = *(const float4*)(vb + (size_t)(j0 + r) * (3 * DD) + c4);
        }
        __syncthreads();

        float sacc[8][4] = {};
#pragma unroll
        for (int kk = 0; kk < 64; kk += 8) {
            uint32_t af[4], bf[8][2];
            af[0] = __float_as_uint(Qs[wrow + g    ][kk + t    ]);
            af[1] = __float_as_uint(Qs[wrow + g + 8][kk + t    ]);
            af[2] = __float_as_uint(Qs[wrow + g    ][kk + t + 4]);
            af[3] = __float_as_uint(Qs[wrow + g + 8][kk + t + 4]);
#pragma unroll
            for (int ni = 0; ni < 8; ni++) {
                int cb = ni * 8 + g;
                bf[ni][0] = __float_as_uint(Ks[cb][kk + t    ]);
                bf[ni][1] = __float_as_uint(Ks[cb][kk + t + 4]);
            }
#pragma unroll
            for (int ni = 0; ni < 8; ni++) {
                asm volatile(
                    "mma.sync.aligned.m16n8k8.row.col.f32.tf32.tf32.f32 "
                    "{%0,%1,%2,%3}, {%4,%5,%6,%7}, {%8,%9}, {%0,%1,%2,%3};"
                    : "+f"(sacc[ni][0]), "+f"(sacc[ni][1]),
                      "+f"(sacc[ni][2]), "+f"(sacc[ni][3])
                    : "r"(af[0]), "r"(af[1]), "r"(af[2]), "r"(af[3]),
                      "r"(bf[ni][0]), "r"(bf[ni][1]));
            }
        }

        int row0 = i0 + wrow + g;
        int row1 = row0 + 8;
#pragma unroll
        for (int ni = 0; ni < 8; ni++) {
            int j = j0 + ni * 8 + 2 * t;
            float km0 = mrow[j], km1 = mrow[j + 1];
            bool ok00 = (j     <= row0) && (km0 != 0.f);
            bool ok01 = (j + 1 <= row0) && (km1 != 0.f);
            bool ok10 = (j     <= row1) && (km0 != 0.f);
            bool ok11 = (j + 1 <= row1) && (km1 != 0.f);
            sacc[ni][0] = ok00 ? sacc[ni][0] * 0.125f : -FMAXV;
            sacc[ni][1] = ok01 ? sacc[ni][1] * 0.125f : -FMAXV;
            sacc[ni][2] = ok10 ? sacc[ni][2] * 0.125f : -FMAXV;
            sacc[ni][3] = ok11 ? sacc[ni][3] * 0.125f : -FMAXV;
        }

        float mx0 = -FMAXV, mx1 = -FMAXV;
#pragma unroll
        for (int ni = 0; ni < 8; ni++) {
            mx0 = fmaxf(mx0, fmaxf(sacc[ni][0], sacc[ni][1]));
            mx1 = fmaxf(mx1, fmaxf(sacc[ni][2], sacc[ni][3]));
        }
        mx0 = fmaxf(mx0, __shfl_xor_sync(0xffffffff, mx0, 1));
        mx0 = fmaxf(mx0, __shfl_xor_sync(0xffffffff, mx0, 2));
        mx1 = fmaxf(mx1, __shfl_xor_sync(0xffffffff, mx1, 1));
        mx1 = fmaxf(mx1, __shfl_xor_sync(0xffffffff, mx1, 2));

        float nm0 = fmaxf(mst0, mx0);
        float nm1 = fmaxf(mst1, mx1);
        float a0 = expf(mst0 - nm0);
        float a1 = expf(mst1 - nm1);
        mst0 = nm0; mst1 = nm1;

        float rs0 = 0.f, rs1 = 0.f;
#pragma unroll
        for (int ni = 0; ni < 8; ni++) {
            float p0 = expf(sacc[ni][0] - nm0);
            float p1 = expf(sacc[ni][1] - nm0);
            float p2 = expf(sacc[ni][2] - nm1);
            float p3 = expf(sacc[ni][3] - nm1);
            sacc[ni][0] = p0; sacc[ni][1] = p1;
            sacc[ni][2] = p2; sacc[ni][3] = p3;
            rs0 += p0 + p1; rs1 += p2 + p3;
        }
        rs0 += __shfl_xor_sync(0xffffffff, rs0, 1);
        rs0 += __shfl_xor_sync(0xffffffff, rs0, 2);
        rs1 += __shfl_xor_sync(0xffffffff, rs1, 1);
        rs1 += __shfl_xor_sync(0xffffffff, rs1, 2);
        lst0 = lst0 * a0 + rs0;
        lst1 = lst1 * a1 + rs1;

#pragma unroll
        for (int ni = 0; ni < 8; ni++) {
            oacc[ni][0] *= a0; oacc[ni][1] *= a0;
            oacc[ni][2] *= a1; oacc[ni][3] *= a1;
        }

#pragma unroll
        for (int ni = 0; ni < 8; ni++) {
            int lc = ni * 8 + 2 * t;
            Ps[wrow + g    ][lc]     = cvt_tf32(sacc[ni][0]);
            Ps[wrow + g    ][lc + 1] = cvt_tf32(sacc[ni][1]);
            Ps[wrow + g + 8][lc]     = cvt_tf32(sacc[ni][2]);
            Ps[wrow + g + 8][lc + 1] = cvt_tf32(sacc[ni][3]);
        }
        __syncwarp();

#pragma unroll
        for (int kk = 0; kk < 64; kk += 8) {
            uint32_t af[4], bf[8][2];
            af[0] = __float_as_uint(Ps[wrow + g    ][kk + t    ]);
            af[1] = __float_as_uint(Ps[wrow + g + 8][kk + t    ]);
            af[2] = __float_as_uint(Ps[wrow + g    ][kk + t + 4]);
            af[3] = __float_as_uint(Ps[wrow + g + 8][kk + t + 4]);
#pragma unroll
            for (int ni = 0; ni < 8; ni++) {
                int cb = ni * 8 + g;
                bf[ni][0] = __float_as_uint(Vs[kk + t    ][cb]);
                bf[ni][1] = __float_as_uint(Vs[kk + t + 4][cb]);
            }
#pragma unroll
            for (int ni = 0; ni < 8; ni++) {
                asm volatile(
                    "mma.sync.aligned.m16n8k8.row.col.f32.tf32.tf32.f32 "
                    "{%0,%1,%2,%3}, {%4,%5,%6,%7}, {%8,%9}, {%0,%1,%2,%3};"
                    : "+f"(oacc[ni][0]), "+f"(oacc[ni][1]),
                      "+f"(oacc[ni][2]), "+f"(oacc[ni][3])
                    : "r"(af[0]), "r"(af[1]), "r"(af[2]), "r"(af[3]),
                      "r"(bf[ni][0]), "r"(bf[ni][1]));
            }
        }
    }

    float* ob = O + (size_t)b * TT * DD + h * DHH;
    int r0 = i0 + wrow + g;
    int r1 = r0 + 8;
    float inv0 = (lst0 > 0.f) ? 1.0f / lst0 : 0.f;
    float inv1 = (lst1 > 0.f) ? 1.0f / lst1 : 0.f;
#pragma unroll
    for (int ni = 0; ni < 8; ni++) {
        int cb = ni * 8 + 2 * t;
        *(float2*)(ob + (size_t)r0 * DD + cb) =
            make_float2(cvt_tf32(oacc[ni][0] * inv0), cvt_tf32(oacc[ni][1] * inv0));
        *(float2*)(ob + (size_t)r1 * DD + cb) =
            make_float2(cvt_tf32(oacc[ni][2] * inv1), cvt_tf32(oacc[ni][3] * inv1));
    }
}

// ---------------------------------------------------------------------------
extern "C" void kernel_launch(void* const* d_in, const int* in_sizes, int n_in,
                              void* d_out, int out_size) {
    const float* x_in    = (const float*)d_in[0];
    const float* m       = (const float*)d_in[1];
    const int*   l       = (const int*)d_in[2];
    const float* Wqkv    = (const float*)d_in[3];
    const float* Wout    = (const float*)d_in[4];
    const float* bout    = (const float*)d_in[5];
    const float* ad_attn = (const float*)d_in[6];
    const float* ad_ffn  = (const float*)d_in[7];
    const float* W1      = (const float*)d_in[8];
    const float* b1      = (const float*)d_in[9];
    const float* W2      = (const float*)d_in[10];
    const float* b2      = (const float*)d_in[11];
    float* x = (float*)d_out;

    float *h, *qkv, *attn, *f1, *wqkv, *wout, *w1, *w2;
    cudaGetSymbolAddress((void**)&h,    g_h);
    cudaGetSymbolAddress((void**)&qkv,  g_qkv);
    cudaGetSymbolAddress((void**)&attn, g_attn);
    cudaGetSymbolAddress((void**)&f1,   g_f1);
    cudaGetSymbolAddress((void**)&wqkv, g_wqkv);
    cudaGetSymbolAddress((void**)&wout, g_wout);
    cudaGetSymbolAddress((void**)&w1,   g_w1);
    cudaGetSymbolAddress((void**)&w2,   g_w2);

    cudaFuncSetAttribute(flash_kernel,
                         cudaFuncAttributeMaxDynamicSharedMemorySize, FA_SMEM);

    cudaMemcpyAsync(x, x_in, sizeof(float) * (size_t)NROWS * DD,
                    cudaMemcpyDeviceToDevice);

    // pre-round all weights to tf32 (bit-identical to per-load cvt)
    round_weights<<<1184, 256>>>(Wqkv, wqkv, NLAY * DD * 3 * DD / 4);
    round_weights<<<1184, 256>>>(Wout, wout, NLAY * DD * DD / 4);
    round_weights<<<1184, 256>>>(W1,   w1,   NLAY * DD * DFF / 4);
    round_weights<<<1184, 256>>>(W2,   w2,   NLAY * DFF * DD / 4);

    for (int i = 0; i < NLAY; i++) {
        // attention sub-block
        adaln_kernel<<<NROWS, 256>>>(x, m, l, ad_attn + (size_t)i * NLEV * 2 * DD, h);
        gemm_tf32<128, 0><<<dim3(3 * DD / 128, NROWS / 128), 256>>>(
            h, wqkv + (size_t)i * DD * 3 * DD, nullptr, nullptr, nullptr,
            qkv, NROWS, 3 * DD, DD);
        flash_kernel<<<dim3(TT / 128, BB * HH), 256, FA_SMEM>>>(qkv, m, attn);
        gemm_tf32<64, 2><<<dim3(DD / 128, NROWS / 64), 256>>>(
            attn, wout + (size_t)i * DD * DD, bout + (size_t)i * DD, x, m,
            x, NROWS, DD, DD);
        // FFN sub-block
        adaln_kernel<<<NROWS, 256>>>(x, m, l, ad_ffn + (size_t)i * NLEV * 2 * DD, h);
        gemm_tf32<128, 1><<<dim3(DFF / 128, NROWS / 128), 256>>>(
            h, w1 + (size_t)i * DD * DFF, b1 + (size_t)i * DFF, nullptr, nullptr,
            f1, NROWS, DFF, DD);
        gemm_tf32<64, 2><<<dim3(DD / 128, NROWS / 64), 256>>>(
            f1, w2 + (size_t)i * DFF * DD, b2 + (size_t)i * DD, x, m,
            x, NROWS, DD, DFF);
    }
}

// round 16
// speedup vs baseline: 1.3514x; 1.3514x over previous
#include <cuda_runtime.h>
#include <cuda_fp16.h>
#include <math.h>
#include <stdint.h>

// Problem constants
#define BB    2
#define TT    1024
#define DD    1024
#define HH    16
#define DHH   64
#define NLAY  4
#define NLEV  8
#define DFF   4096
#define NROWS (BB*TT)
#define FMAXV 3.402823466e38f

// Scratch (device globals — no allocation allowed)
__device__ __half g_h[NROWS * DD];            // adaln out (fp16, GEMM A operand)
__device__ float  g_qkv[NROWS * 3 * DD];      // qkv (fp32/tf32, flash input)
__device__ __half g_attn[NROWS * DD];         // flash out (fp16, GEMM A operand)
__device__ __half g_f1[NROWS * DFF];          // gelu out (fp16, GEMM A operand)
// fp16 transposed weights: Wt[n][k] per layer
__device__ __half g_wqkvT[NLAY * 3 * DD * DD];
__device__ __half g_woutT[NLAY * DD * DD];
__device__ __half g_w1T[NLAY * DFF * DD];
__device__ __half g_w2T[NLAY * DD * DFF];

__device__ __forceinline__ float gelu_exact(float x) {
    return 0.5f * x * (1.0f + erff(x * 0.70710678118654752f));
}
__device__ __forceinline__ float cvt_tf32(float x) {
    uint32_t u;
    asm("cvt.rna.tf32.f32 %0, %1;" : "=r"(u) : "f"(x));
    return __uint_as_float(u);
}
__device__ __forceinline__ void cp_async16(uint32_t smem, const void* gmem) {
    asm volatile("cp.async.cg.shared.global [%0], [%1], 16;" :: "r"(smem), "l"(gmem));
}

// ---------------------------------------------------------------------------
// Weight prep: in [L-slice][K][N] fp32 -> out [N][K] fp16 (transposed)
// ---------------------------------------------------------------------------
__global__ void half_transpose(const float* __restrict__ in, __half* __restrict__ out,
                               int K, int N) {
    __shared__ float tile[32][33];
    const float* pin = in + (size_t)blockIdx.z * K * N;
    __half* pout = out + (size_t)blockIdx.z * K * N;
    int n0 = blockIdx.x * 32, k0 = blockIdx.y * 32;
    int tx = threadIdx.x & 31, ty = threadIdx.x >> 5;   // 256 thr
#pragma unroll
    for (int dy = 0; dy < 32; dy += 8)
        tile[ty + dy][tx] = pin[(size_t)(k0 + ty + dy) * N + n0 + tx];
    __syncthreads();
#pragma unroll
    for (int dy = 0; dy < 32; dy += 8)
        pout[(size_t)(n0 + ty + dy) * K + k0 + tx] = __float2half_rn(tile[tx][ty + dy]);
}

// ---------------------------------------------------------------------------
// AdaLN (fp16 output — feeds GEMM A operands only)
// ---------------------------------------------------------------------------
__global__ void adaln_kernel(const float* __restrict__ x, const float* __restrict__ m,
                             const int* __restrict__ l, const float* __restrict__ emb,
                             __half* __restrict__ out) {
    int row = blockIdx.x;
    int b = row / TT;
    float mv = m[row];
    const float* xr = x + (size_t)row * DD;
    __half* orow = out + (size_t)row * DD;
    int tid = threadIdx.x;

    float v[4];
    float s = 0.f, ss = 0.f;
#pragma unroll
    for (int u = 0; u < 4; u++) {
        v[u] = xr[tid + u * 256];
        s += v[u];
        ss += v[u] * v[u];
    }
    __shared__ float sh1[256];
    __shared__ float sh2[256];
    sh1[tid] = s; sh2[tid] = ss;
    __syncthreads();
    for (int stp = 128; stp > 0; stp >>= 1) {
        if (tid < stp) { sh1[tid] += sh1[tid + stp]; sh2[tid] += sh2[tid + stp]; }
        __syncthreads();
    }
    float mu  = sh1[0] * (1.0f / DD);
    float var = sh2[0] * (1.0f / DD) - mu * mu;
    float rinv = rsqrtf(var + 1e-5f);

    const float* g = emb + (size_t)l[b] * (2 * DD);
#pragma unroll
    for (int u = 0; u < 4; u++) {
        int d = tid + u * 256;
        float hn = (v[u] - mu) * rinv;
        float h = 2.0f * (1.0f - 0.1f * hn) * hn;
        orow[d] = __float2half_rn((expf(g[d]) * h + g[DD + d]) * mv);
    }
}

// ---------------------------------------------------------------------------
// fp16 tensor-core GEMM (mma.m16n8k16), 2-stage cp.async pipeline.
// C[M,N] = epi(A[M,K] @ Wt[N,K]^T + bias).  A, Wt are fp16; accum fp32.
// CTA 128x128, BK=64 (4 k16 phases), 256 thr, 8 warps (2x4), warp 64x32.
// smem halves: As[2][128][72] | Bs[2][128][72]  (72-stride -> conflict-free)
// EPI: 0 none (tf32-rounded fp32 store), 1 GELU (fp16 store), 2 residual+mask
// ---------------------------------------------------------------------------
#define HSTRIDE 72
#define STAGE_H (128 * HSTRIDE)                 // halves per tile
#define GEMM_SMEM (4 * STAGE_H * 2)             // bytes: 2 stages x 2 tiles

template <int EPI, typename OUT>
__global__ void __launch_bounds__(256, 2)
gemm_fp16(const __half* __restrict__ A, const __half* __restrict__ Wt,
          const float* __restrict__ bias, const float* __restrict__ res,
          const float* __restrict__ m, OUT* __restrict__ C,
          int M, int N, int K) {
    extern __shared__ __align__(16) __half smh[];
    __half* AS[2] = { smh,             smh + STAGE_H };
    __half* BS[2] = { smh + 2*STAGE_H, smh + 3*STAGE_H };

    int tid  = threadIdx.x;
    int warp = tid >> 5, lane = tid & 31;
    int g = lane >> 2, t = lane & 3;
    int warpm = warp >> 2, warpn = warp & 3;   // 2 x 4 warps, warp tile 64x32
    int row0 = blockIdx.y * 128, n0 = blockIdx.x * 128;

    float acc[4][4][4] = {};

    int lr = tid >> 3;          // 0..31 (+32j): row within tile
    int lc = tid & 7;           // 16B chunk (8 halves) within 128B row

#define ISSUE_TILE(buf, k0)                                                       \
    {                                                                             \
        _Pragma("unroll")                                                         \
        for (int j = 0; j < 4; j++) {                                             \
            int r = lr + j * 32;                                                  \
            cp_async16((uint32_t)__cvta_generic_to_shared(                        \
                           AS[buf] + r * HSTRIDE + lc * 8),                       \
                       A + (size_t)(row0 + r) * K + (k0) + lc * 8);               \
            cp_async16((uint32_t)__cvta_generic_to_shared(                        \
                           BS[buf] + r * HSTRIDE + lc * 8),                       \
                       Wt + (size_t)(n0 + r) * K + (k0) + lc * 8);                \
        }                                                                         \
        asm volatile("cp.async.commit_group;");                                   \
    }

    int NC = K / 64;
    ISSUE_TILE(0, 0)
    ISSUE_TILE(1, 64)

    for (int c = 0; c < NC; c++) {
        if (c < NC - 1) {
            asm volatile("cp.async.wait_group 1;");
        } else {
            asm volatile("cp.async.wait_group 0;");
        }
        __syncthreads();
        int buf = c & 1;

#pragma unroll
        for (int kk = 0; kk < 64; kk += 16) {
            uint32_t af[4][4], bf[4][2];
#pragma unroll
            for (int mi = 0; mi < 4; mi++) {
                int rb = warpm * 64 + mi * 16 + g;
                const __half* ab = AS[buf] + rb * HSTRIDE + kk + 2 * t;
                af[mi][0] = *(const uint32_t*)(ab);
                af[mi][1] = *(const uint32_t*)(ab + 8 * HSTRIDE);
                af[mi][2] = *(const uint32_t*)(ab + 8);
                af[mi][3] = *(const uint32_t*)(ab + 8 * HSTRIDE + 8);
            }
#pragma unroll
            for (int ni = 0; ni < 4; ni++) {
                int cb = warpn * 32 + ni * 8 + g;
                const __half* bb = BS[buf] + cb * HSTRIDE + kk + 2 * t;
                bf[ni][0] = *(const uint32_t*)(bb);
                bf[ni][1] = *(const uint32_t*)(bb + 8);
            }
#pragma unroll
            for (int mi = 0; mi < 4; mi++)
#pragma unroll
                for (int ni = 0; ni < 4; ni++) {
                    asm volatile(
                        "mma.sync.aligned.m16n8k16.row.col.f32.f16.f16.f32 "
                        "{%0,%1,%2,%3}, {%4,%5,%6,%7}, {%8,%9}, {%0,%1,%2,%3};"
                        : "+f"(acc[mi][ni][0]), "+f"(acc[mi][ni][1]),
                          "+f"(acc[mi][ni][2]), "+f"(acc[mi][ni][3])
                        : "r"(af[mi][0]), "r"(af[mi][1]), "r"(af[mi][2]), "r"(af[mi][3]),
                          "r"(bf[ni][0]), "r"(bf[ni][1]));
                }
        }
        __syncthreads();
        if (c + 2 < NC) {
            ISSUE_TILE(buf, (c + 2) * 64)
        }
    }
#undef ISSUE_TILE

#pragma unroll
    for (int mi = 0; mi < 4; mi++) {
        int r0 = row0 + warpm * 64 + mi * 16 + g;
        int r1 = r0 + 8;
        float m0 = (EPI == 2) ? m[r0] : 0.f;
        float m1 = (EPI == 2) ? m[r1] : 0.f;
#pragma unroll
        for (int ni = 0; ni < 4; ni++) {
            int cb = n0 + warpn * 32 + ni * 8 + 2 * t;
            float v0 = acc[mi][ni][0], v1 = acc[mi][ni][1];
            float v2 = acc[mi][ni][2], v3 = acc[mi][ni][3];
            if (bias) {
                float b0 = bias[cb], b1 = bias[cb + 1];
                v0 += b0; v1 += b1; v2 += b0; v3 += b1;
            }
            if (EPI == 1) {
                v0 = gelu_exact(v0); v1 = gelu_exact(v1);
                v2 = gelu_exact(v2); v3 = gelu_exact(v3);
            }
            if (EPI == 2) {
                const float* rr0 = res + (size_t)r0 * N + cb;
                const float* rr1 = res + (size_t)r1 * N + cb;
                v0 = (rr0[0] + v0) * m0; v1 = (rr0[1] + v1) * m0;
                v2 = (rr1[0] + v2) * m1; v3 = (rr1[1] + v3) * m1;
            }
            if constexpr (sizeof(OUT) == 2) {
                *(__half2*)(C + (size_t)r0 * N + cb) = __floats2half2_rn(v0, v1);
                *(__half2*)(C + (size_t)r1 * N + cb) = __floats2half2_rn(v2, v3);
            } else {
                if (EPI == 0) {
                    v0 = cvt_tf32(v0); v1 = cvt_tf32(v1);
                    v2 = cvt_tf32(v2); v3 = cvt_tf32(v3);
                }
                *(float2*)(C + (size_t)r0 * N + cb) = make_float2(v0, v1);
                *(float2*)(C + (size_t)r1 * N + cb) = make_float2(v2, v3);
            }
        }
    }
}

// ---------------------------------------------------------------------------
// Flash attention (tf32 legacy MMA) — unchanged math; output stored fp16.
// ---------------------------------------------------------------------------
#define FA_SMEM ((128*68 + 64*68 + 64*68 + 128*68) * 4)

__global__ void __launch_bounds__(256)
flash_kernel(const float* __restrict__ qkv, const float* __restrict__ mk,
             __half* __restrict__ O) {
    extern __shared__ float sm[];
    float (*Qs)[68] = (float(*)[68])sm;
    float (*Ks)[68] = (float(*)[68])(sm + 128 * 68);
    float (*Vs)[68] = (float(*)[68])(sm + 128 * 68 + 64 * 68);
    float (*Ps)[68] = (float(*)[68])(sm + 128 * 68 + 2 * 64 * 68);

    int z = blockIdx.y; int b = z >> 4; int h = z & 15;
    int it = gridDim.x - 1 - blockIdx.x;
    int i0 = it * 128;
    int tid = threadIdx.x;
    int warp = tid >> 5, lane = tid & 31;
    int g = lane >> 2, t = lane & 3;
    int wrow = warp * 16;

    const float* qb = qkv + (size_t)b * TT * 3 * DD + h * DHH;
    const float* kb = qb + DD;
    const float* vb = qb + 2 * DD;
    const float* mrow = mk + b * TT;

#pragma unroll
    for (int i = 0; i < 8; i++) {
        int idx = tid + i * 256;
        int r = idx >> 4, c4 = (idx & 15) * 4;
        *(float4*)&Qs[r][c4] = *(const float4*)(qb + (size_t)(i0 + r) * (3 * DD) + c4);
    }

    float oacc[8][4] = {};
    float mst0 = -FMAXV, mst1 = -FMAXV;
    float lst0 = 0.f,    lst1 = 0.f;

    int jend = i0 + 128;
    for (int j0 = 0; j0 < jend; j0 += 64) {
        __syncthreads();
#pragma unroll
        for (int i = 0; i < 4; i++) {
            int idx = tid + i * 256;
            int r = idx >> 4, c4 = (idx & 15) * 4;
            *(float4*)&Ks[r][c4] = *(const float4*)(kb + (size_t)(j0 + r) * (3 * DD) + c4);
            *(float4*)&Vs[r][c4] = *(const float4*)(vb + (size_t)(j0 + r) * (3 * DD) + c4);
        }
        __syncthreads();

        float sacc[8][4] = {};
#pragma unroll
        for (int kk = 0; kk < 64; kk += 8) {
            uint32_t af[4], bf[8][2];
            af[0] = __float_as_uint(Qs[wrow + g    ][kk + t    ]);
            af[1] = __float_as_uint(Qs[wrow + g + 8][kk + t    ]);
            af[2] = __float_as_uint(Qs[wrow + g    ][kk + t + 4]);
            af[3] = __float_as_uint(Qs[wrow + g + 8][kk + t + 4]);
#pragma unroll
            for (int ni = 0; ni < 8; ni++) {
                int cb = ni * 8 + g;
                bf[ni][0] = __float_as_uint(Ks[cb][kk + t    ]);
                bf[ni][1] = __float_as_uint(Ks[cb][kk + t + 4]);
            }
#pragma unroll
            for (int ni = 0; ni < 8; ni++) {
                asm volatile(
                    "mma.sync.aligned.m16n8k8.row.col.f32.tf32.tf32.f32 "
                    "{%0,%1,%2,%3}, {%4,%5,%6,%7}, {%8,%9}, {%0,%1,%2,%3};"
                    : "+f"(sacc[ni][0]), "+f"(sacc[ni][1]),
                      "+f"(sacc[ni][2]), "+f"(sacc[ni][3])
                    : "r"(af[0]), "r"(af[1]), "r"(af[2]), "r"(af[3]),
                      "r"(bf[ni][0]), "r"(bf[ni][1]));
            }
        }

        int row0 = i0 + wrow + g;
        int row1 = row0 + 8;
#pragma unroll
        for (int ni = 0; ni < 8; ni++) {
            int j = j0 + ni * 8 + 2 * t;
            float km0 = mrow[j], km1 = mrow[j + 1];
            bool ok00 = (j     <= row0) && (km0 != 0.f);
            bool ok01 = (j + 1 <= row0) && (km1 != 0.f);
            bool ok10 = (j     <= row1) && (km0 != 0.f);
            bool ok11 = (j + 1 <= row1) && (km1 != 0.f);
            sacc[ni][0] = ok00 ? sacc[ni][0] * 0.125f : -FMAXV;
            sacc[ni][1] = ok01 ? sacc[ni][1] * 0.125f : -FMAXV;
            sacc[ni][2] = ok10 ? sacc[ni][2] * 0.125f : -FMAXV;
            sacc[ni][3] = ok11 ? sacc[ni][3] * 0.125f : -FMAXV;
        }

        float mx0 = -FMAXV, mx1 = -FMAXV;
#pragma unroll
        for (int ni = 0; ni < 8; ni++) {
            mx0 = fmaxf(mx0, fmaxf(sacc[ni][0], sacc[ni][1]));
            mx1 = fmaxf(mx1, fmaxf(sacc[ni][2], sacc[ni][3]));
        }
        mx0 = fmaxf(mx0, __shfl_xor_sync(0xffffffff, mx0, 1));
        mx0 = fmaxf(mx0, __shfl_xor_sync(0xffffffff, mx0, 2));
        mx1 = fmaxf(mx1, __shfl_xor_sync(0xffffffff, mx1, 1));
        mx1 = fmaxf(mx1, __shfl_xor_sync(0xffffffff, mx1, 2));

        float nm0 = fmaxf(mst0, mx0);
        float nm1 = fmaxf(mst1, mx1);
        float a0 = expf(mst0 - nm0);
        float a1 = expf(mst1 - nm1);
        mst0 = nm0; mst1 = nm1;

        float rs0 = 0.f, rs1 = 0.f;
#pragma unroll
        for (int ni = 0; ni < 8; ni++) {
            float p0 = expf(sacc[ni][0] - nm0);
            float p1 = expf(sacc[ni][1] - nm0);
            float p2 = expf(sacc[ni][2] - nm1);
            float p3 = expf(sacc[ni][3] - nm1);
            sacc[ni][0] = p0; sacc[ni][1] = p1;
            sacc[ni][2] = p2; sacc[ni][3] = p3;
            rs0 += p0 + p1; rs1 += p2 + p3;
        }
        rs0 += __shfl_xor_sync(0xffffffff, rs0, 1);
        rs0 += __shfl_xor_sync(0xffffffff, rs0, 2);
        rs1 += __shfl_xor_sync(0xffffffff, rs1, 1);
        rs1 += __shfl_xor_sync(0xffffffff, rs1, 2);
        lst0 = lst0 * a0 + rs0;
        lst1 = lst1 * a1 + rs1;

#pragma unroll
        for (int ni = 0; ni < 8; ni++) {
            oacc[ni][0] *= a0; oacc[ni][1] *= a0;
            oacc[ni][2] *= a1; oacc[ni][3] *= a1;
        }

#pragma unroll
        for (int ni = 0; ni < 8; ni++) {
            int lc = ni * 8 + 2 * t;
            Ps[wrow + g    ][lc]     = cvt_tf32(sacc[ni][0]);
            Ps[wrow + g    ][lc + 1] = cvt_tf32(sacc[ni][1]);
            Ps[wrow + g + 8][lc]     = cvt_tf32(sacc[ni][2]);
            Ps[wrow + g + 8][lc + 1] = cvt_tf32(sacc[ni][3]);
        }
        __syncwarp();

#pragma unroll
        for (int kk = 0; kk < 64; kk += 8) {
            uint32_t af[4], bf[8][2];
            af[0] = __float_as_uint(Ps[wrow + g    ][kk + t    ]);
            af[1] = __float_as_uint(Ps[wrow + g + 8][kk + t    ]);
            af[2] = __float_as_uint(Ps[wrow + g    ][kk + t + 4]);
            af[3] = __float_as_uint(Ps[wrow + g + 8][kk + t + 4]);
#pragma unroll
            for (int ni = 0; ni < 8; ni++) {
                int cb = ni * 8 + g;
                bf[ni][0] = __float_as_uint(Vs[kk + t    ][cb]);
                bf[ni][1] = __float_as_uint(Vs[kk + t + 4][cb]);
            }
#pragma unroll
            for (int ni = 0; ni < 8; ni++) {
                asm volatile(
                    "mma.sync.aligned.m16n8k8.row.col.f32.tf32.tf32.f32 "
                    "{%0,%1,%2,%3}, {%4,%5,%6,%7}, {%8,%9}, {%0,%1,%2,%3};"
                    : "+f"(oacc[ni][0]), "+f"(oacc[ni][1]),
                      "+f"(oacc[ni][2]), "+f"(oacc[ni][3])
                    : "r"(af[0]), "r"(af[1]), "r"(af[2]), "r"(af[3]),
                      "r"(bf[ni][0]), "r"(bf[ni][1]));
            }
        }
    }

    // epilogue: O / l -> g_attn as fp16 (feeds Wout GEMM A)
    __half* ob = O + (size_t)b * TT * DD + h * DHH;
    int r0 = i0 + wrow + g;
    int r1 = r0 + 8;
    float inv0 = (lst0 > 0.f) ? 1.0f / lst0 : 0.f;
    float inv1 = (lst1 > 0.f) ? 1.0f / lst1 : 0.f;
#pragma unroll
    for (int ni = 0; ni < 8; ni++) {
        int cb = ni * 8 + 2 * t;
        *(__half2*)(ob + (size_t)r0 * DD + cb) =
            __floats2half2_rn(oacc[ni][0] * inv0, oacc[ni][1] * inv0);
        *(__half2*)(ob + (size_t)r1 * DD + cb) =
            __floats2half2_rn(oacc[ni][2] * inv1, oacc[ni][3] * inv1);
    }
}

// ---------------------------------------------------------------------------
extern "C" void kernel_launch(void* const* d_in, const int* in_sizes, int n_in,
                              void* d_out, int out_size) {
    const float* x_in    = (const float*)d_in[0];
    const float* m       = (const float*)d_in[1];
    const int*   l       = (const int*)d_in[2];
    const float* Wqkv    = (const float*)d_in[3];
    const float* Wout    = (const float*)d_in[4];
    const float* bout    = (const float*)d_in[5];
    const float* ad_attn = (const float*)d_in[6];
    const float* ad_ffn  = (const float*)d_in[7];
    const float* W1      = (const float*)d_in[8];
    const float* b1      = (const float*)d_in[9];
    const float* W2      = (const float*)d_in[10];
    const float* b2      = (const float*)d_in[11];
    float* x = (float*)d_out;

    __half *h, *attn, *f1, *wqkvT, *woutT, *w1T, *w2T;
    float *qkv;
    cudaGetSymbolAddress((void**)&h,     g_h);
    cudaGetSymbolAddress((void**)&qkv,   g_qkv);
    cudaGetSymbolAddress((void**)&attn,  g_attn);
    cudaGetSymbolAddress((void**)&f1,    g_f1);
    cudaGetSymbolAddress((void**)&wqkvT, g_wqkvT);
    cudaGetSymbolAddress((void**)&woutT, g_woutT);
    cudaGetSymbolAddress((void**)&w1T,   g_w1T);
    cudaGetSymbolAddress((void**)&w2T,   g_w2T);

    cudaFuncSetAttribute(flash_kernel,
                         cudaFuncAttributeMaxDynamicSharedMemorySize, FA_SMEM);
    cudaFuncSetAttribute(gemm_fp16<0, float>,
                         cudaFuncAttributeMaxDynamicSharedMemorySize, GEMM_SMEM);
    cudaFuncSetAttribute(gemm_fp16<1, __half>,
                         cudaFuncAttributeMaxDynamicSharedMemorySize, GEMM_SMEM);
    cudaFuncSetAttribute(gemm_fp16<2, float>,
                         cudaFuncAttributeMaxDynamicSharedMemorySize, GEMM_SMEM);

    cudaMemcpyAsync(x, x_in, sizeof(float) * (size_t)NROWS * DD,
                    cudaMemcpyDeviceToDevice);

    // weights -> fp16, transposed to [n][k]
    half_transpose<<<dim3(3 * DD / 32, DD / 32, NLAY), 256>>>(Wqkv, wqkvT, DD, 3 * DD);
    half_transpose<<<dim3(DD / 32, DD / 32, NLAY), 256>>>(Wout, woutT, DD, DD);
    half_transpose<<<dim3(DFF / 32, DD / 32, NLAY), 256>>>(W1, w1T, DD, DFF);
    half_transpose<<<dim3(DD / 32, DFF / 32, NLAY), 256>>>(W2, w2T, DFF, DD);

    for (int i = 0; i < NLAY; i++) {
        // attention sub-block
        adaln_kernel<<<NROWS, 256>>>(x, m, l, ad_attn + (size_t)i * NLEV * 2 * DD, h);
        gemm_fp16<0, float><<<dim3(3 * DD / 128, NROWS / 128), 256, GEMM_SMEM>>>(
            h, wqkvT + (size_t)i * DD * 3 * DD, nullptr, nullptr, nullptr,
            qkv, NROWS, 3 * DD, DD);
        flash_kernel<<<dim3(TT / 128, BB * HH), 256, FA_SMEM>>>(qkv, m, attn);
        gemm_fp16<2, float><<<dim3(DD / 128, NROWS / 128), 256, GEMM_SMEM>>>(
            attn, woutT + (size_t)i * DD * DD, bout + (size_t)i * DD, x, m,
            x, NROWS, DD, DD);
        // FFN sub-block
        adaln_kernel<<<NROWS, 256>>>(x, m, l, ad_ffn + (size_t)i * NLEV * 2 * DD, h);
        gemm_fp16<1, __half><<<dim3(DFF / 128, NROWS / 128), 256, GEMM_SMEM>>>(
            h, w1T + (size_t)i * DD * DFF, b1 + (size_t)i * DFF, nullptr, nullptr,
            f1, NROWS, DFF, DD);
        gemm_fp16<2, float><<<dim3(DD / 128, NROWS / 128), 256, GEMM_SMEM>>>(
            f1, w2T + (size_t)i * DFF * DD, b2 + (size_t)i * DD, x, m,
            x, NROWS, DD, DFF);
    }
}